// round 10
// baseline (speedup 1.0000x reference)
#include <cuda_runtime.h>

// Problem constants (B=4, N_obj=8 -> 32 objects, N_v=2048 points, 64 anchors, 16-NN)
#define N_V        2048
#define N_OBJS     32
#define ANCHORS    64
#define KNN        16
#define THREADS    256
#define PPT        8            // points per thread in FPS (2048/256)
#define FULL       0xffffffffu

// per-anchor pack: (qx, qy, qz, bitcast(anchor_index)); published incrementally by FPS
__device__ float4   g_qpack[N_OBJS * ANCHORS];
__device__ unsigned g_ready[N_OBJS];          // zero-initialized at module load

__device__ __forceinline__ void st_release_u32(unsigned* p, unsigned v) {
    asm volatile("st.release.gpu.global.u32 [%0], %1;" :: "l"(p), "r"(v) : "memory");
}
__device__ __forceinline__ unsigned ld_acquire_u32(const unsigned* p) {
    unsigned v;
    asm volatile("ld.acquire.gpu.global.u32 %0, [%1];" : "=r"(v) : "l"(p) : "memory");
    return v;
}

// monotonic total-order key for floats (handles tiny negative d2 from cancellation)
__device__ __forceinline__ unsigned fkey(float f) {
    const unsigned u = __float_as_uint(f);
    return (u & 0x80000000u) ? ~u : (u | 0x80000000u);
}

struct FpsSm {
    float spts[N_V * 3];                      // 24 KB
    unsigned long long swk[2][THREADS / 32];
};
struct KnnSm {
    float dsh[KNN][256];                      // 16 KB distance park (both halves)
    float cand[2][4 * KNN];
    float psum[2][4][3];
    float sT[2];
};
union SmU { FpsSm f; KnnSm k; };

// ---------------------------------------------------------------------------
// Fused kernel. Blocks 0..31: FPS (one object each, R2-proven body) that
// PUBLISHES each anchor as soon as it is final (release store). Blocks 32+:
// KNN for two anchors (two independent 128-thread halves, R4-proven
// selection) that ACQUIRE-wait for their anchor, overlapping with FPS.
// Replay-safe: FPS rewrites byte-identical values, so stale reads are
// equal to fresh reads; first launch is ordered by release/acquire.
// ---------------------------------------------------------------------------
__global__ __launch_bounds__(THREADS) void fused_kernel(const float* __restrict__ pos,
                                                        const float* __restrict__ vel,
                                                        const float* __restrict__ phys,
                                                        const float* __restrict__ refp,
                                                        float* __restrict__ out) {
    __shared__ SmU sm;
    const int bid = blockIdx.x;
    const int tid = threadIdx.x;

    if (bid < N_OBJS) {
        // ================= FPS path (R2 body + incremental publish) =========
        const int o = bid;
        const float* __restrict__ P = pos + (size_t)o * N_V * 3;
        float* spts = sm.f.spts;

        const int lane = tid & 31;
        const int wid  = tid >> 5;

        for (int i = tid; i < N_V * 3; i += THREADS) spts[i] = P[i];
        __syncthreads();

        float px[PPT], py[PPT], pz[PPT], md[PPT];
        const float x0 = spts[0], y0 = spts[1], z0 = spts[2];
#pragma unroll
        for (int k = 0; k < PPT; k++) {
            const int j = tid + THREADS * k;
            px[k] = spts[j * 3 + 0];
            py[k] = spts[j * 3 + 1];
            pz[k] = spts[j * 3 + 2];
            const float dx = px[k] - x0, dy = py[k] - y0, dz = pz[k] - z0;
            md[k] = dx * dx + dy * dy + dz * dz;          // matches reference FPS formula
        }
        if (tid == 0) {                                   // publish anchor 0
            g_qpack[o * ANCHORS + 0] = make_float4(x0, y0, z0, __int_as_float(0));
            st_release_u32(&g_ready[o], 1u);
        }

        int buf = 0;
        for (int it = 1; it < ANCHORS; ++it) {
            // local argmax over my 8 points
            float bv = md[0];
            int   bi = tid;
#pragma unroll
            for (int k = 1; k < PPT; k++) {
                if (md[k] > bv) { bv = md[k]; bi = tid + THREADS * k; }
            }
            // warp argmax (tie-safe ballot+ffs single winner)
            const unsigned u   = __float_as_uint(bv);
            const unsigned m   = __reduce_max_sync(FULL, u);
            const unsigned bal = __ballot_sync(FULL, u == m);
            const int src = __ffs(bal) - 1;
            const int ci  = __shfl_sync(FULL, bi, src);
            if (lane == 0)
                sm.f.swk[buf][wid] =
                    ((unsigned long long)m << 32) | (unsigned)(0x7FFFFFFF - ci);
            __syncthreads();

            unsigned long long best = sm.f.swk[buf][0];
#pragma unroll
            for (int w = 1; w < THREADS / 32; w++) {
                const unsigned long long c = sm.f.swk[buf][w];
                if (c > best) best = c;
            }
            const int bidx = 0x7FFFFFFF - (int)(unsigned)(best & 0xFFFFFFFFull);

            const float qx = spts[bidx * 3 + 0];
            const float qy = spts[bidx * 3 + 1];
            const float qz = spts[bidx * 3 + 2];
            if (tid == 0) {                               // publish anchor `it`
                g_qpack[o * ANCHORS + it] =
                    make_float4(qx, qy, qz, __int_as_float(bidx));
                st_release_u32(&g_ready[o], (unsigned)(it + 1));
            }
#pragma unroll
            for (int k = 0; k < PPT; k++) {
                const float dx = px[k] - qx, dy = py[k] - qy, dz = pz[k] - qz;
                const float d = dx * dx + dy * dy + dz * dz;
                md[k] = fminf(md[k], d);
            }
            buf ^= 1;
        }
        return;
    }

    // ==================== KNN path: two anchors per block ====================
    const int half = tid >> 7;                   // 0 or 1
    const int t    = tid & 127;                  // tid within half
    const int lane = t & 31;
    const int wid  = (t >> 5) & 3;
    const int a    = (bid - N_OBJS) * 2 + half;  // global anchor id [0, 2048)
    const int obj  = a >> 6;
    const int aloc = a & 63;

    // ---- acquire-wait for my anchor ----
    while (ld_acquire_u32(&g_ready[obj]) <= (unsigned)aloc) __nanosleep(256);
    const float4 qp = g_qpack[a];                // ordered after acquire
    const float qx = qp.x, qy = qp.y, qz = qp.z;
    const int aidx = __float_as_int(qp.w);
    const float sqq = qx * qx + qy * qy + qz * qz;

    // ---- independent output fields o[3..11] (warp 1 lane 0, off critical path)
    if (t == 32) {
        float* __restrict__ op = out + (size_t)a * 12;
        const float* __restrict__ V = vel  + (size_t)obj * N_V * 3;
        const float* __restrict__ R = refp + (size_t)obj * N_V * 3;
        op[3] = V[aidx * 3 + 0];
        op[4] = V[aidx * 3 + 1];
        op[5] = V[aidx * 3 + 2];
        op[6] = qx - R[aidx * 3 + 0];
        op[7] = qy - R[aidx * 3 + 1];
        op[8] = qz - R[aidx * 3 + 2];
        op[9]  = phys[obj * 3 + 0];
        op[10] = phys[obj * 3 + 1];
        op[11] = phys[obj * 3 + 2];
    }

    const float* __restrict__ P = pos + (size_t)obj * N_V * 3;
    const int base = wid << 9;                   // this warp's 512-point chunk

    // ---- distances for my 16 points (expression identical to R2) ----
    float v[KNN];
#pragma unroll 4
    for (int k = 0; k < KNN; k++) {
        const int j = base + (k << 5) + lane;
        const float x = P[j * 3 + 0], y = P[j * 3 + 1], z = P[j * 3 + 2];
        float dd = (x * x + y * y + z * z + sqq) - 2.0f * (x * qx + y * qy + z * qz);
        if (j == aidx) dd += 1e10f;              // reference's diagonal exclusion
        v[k] = dd;
        sm.k.dsh[k][tid] = dd;
    }

    // ---- bitonic sort of the 16 values (ascending), value-only ----
#pragma unroll
    for (int kk = 2; kk <= KNN; kk <<= 1) {
#pragma unroll
        for (int jj = kk >> 1; jj > 0; jj >>= 1) {
#pragma unroll
            for (int i = 0; i < KNN; i++) {
                const int l = i ^ jj;
                if (l > i) {
                    const float va = v[i], vb = v[l];
                    const float lo = fminf(va, vb), hi = fmaxf(va, vb);
                    const bool up = ((i & kk) == 0);
                    v[i] = up ? lo : hi;
                    v[l] = up ? hi : lo;
                }
            }
        }
    }

    // ---- per-warp pop-min extraction: 16 smallest of this warp's 512 ----
    const float FINF = __int_as_float(0x7f800000);
#pragma unroll
    for (int r = 0; r < KNN; r++) {
        const unsigned key = fkey(v[0]);
        const unsigned km  = __reduce_min_sync(FULL, key);
        const unsigned bal = __ballot_sync(FULL, key == km);
        const int win = __ffs(bal) - 1;
        if (lane == win) {
            sm.k.cand[half][(wid << 4) + r] = v[0];
#pragma unroll
            for (int tt = 0; tt < KNN - 1; tt++) v[tt] = v[tt + 1];
            v[KNN - 1] = FINF;
        }
    }
    __syncthreads();

    // ---- warp 0 of each half: T = 16th smallest of the 64 candidates ----
    if (wid == 0) {
        float c0 = sm.k.cand[half][lane * 2], c1 = sm.k.cand[half][lane * 2 + 1];
        float T = 0.0f;
#pragma unroll
        for (int r = 0; r < KNN; r++) {
            const unsigned key = fkey(c0);
            const unsigned km  = __reduce_min_sync(FULL, key);
            const unsigned bal = __ballot_sync(FULL, key == km);
            const int win = __ffs(bal) - 1;
            T = __shfl_sync(FULL, c0, win);
            if (lane == win) { c0 = c1; c1 = FINF; }
        }
        if (lane == 0) sm.k.sT[half] = T;
    }
    __syncthreads();
    const float T = sm.k.sT[half];

    // ---- accumulate positions of the 16 selected points ----
    float sx = 0.f, sy = 0.f, sz = 0.f;
#pragma unroll 4
    for (int k = 0; k < KNN; k++) {
        if (sm.k.dsh[k][tid] <= T) {
            const int j = base + (k << 5) + lane;
            sx += P[j * 3 + 0];
            sy += P[j * 3 + 1];
            sz += P[j * 3 + 2];
        }
    }
#pragma unroll
    for (int off = 16; off; off >>= 1) {
        sx += __shfl_xor_sync(FULL, sx, off);
        sy += __shfl_xor_sync(FULL, sy, off);
        sz += __shfl_xor_sync(FULL, sz, off);
    }
    if (lane == 0) {
        sm.k.psum[half][wid][0] = sx;
        sm.k.psum[half][wid][1] = sy;
        sm.k.psum[half][wid][2] = sz;
    }
    __syncthreads();

    if (t == 0) {
        const float nx = sm.k.psum[half][0][0] + sm.k.psum[half][1][0] +
                         sm.k.psum[half][2][0] + sm.k.psum[half][3][0];
        const float ny = sm.k.psum[half][0][1] + sm.k.psum[half][1][1] +
                         sm.k.psum[half][2][1] + sm.k.psum[half][3][1];
        const float nz = sm.k.psum[half][0][2] + sm.k.psum[half][1][2] +
                         sm.k.psum[half][2][2] + sm.k.psum[half][3][2];
        float* __restrict__ o = out + (size_t)a * 12;
        const float inv = 1.0f / 16.0f;
        o[0] = nx * inv - qx;                    // anchor_dist: mean(neigh) - p
        o[1] = ny * inv - qy;
        o[2] = nz * inv - qz;
    }
}

extern "C" void kernel_launch(void* const* d_in, const int* in_sizes, int n_in,
                              void* d_out, int out_size) {
    const float* positions  = (const float*)d_in[0];
    const float* velocities = (const float*)d_in[1];
    const float* physics    = (const float*)d_in[2];
    const float* refpos     = (const float*)d_in[3];
    float* out = (float*)d_out;

    const int grid = N_OBJS + (N_OBJS * ANCHORS) / 2;     // 32 fps + 1024 knn blocks
    fused_kernel<<<grid, THREADS>>>(positions, velocities, physics, refpos, out);
}

// round 11
// speedup vs baseline: 4.6829x; 4.6829x over previous
#include <cuda_runtime.h>

// Problem constants (B=4, N_obj=8 -> 32 objects, N_v=2048 points, 64 anchors, 16-NN)
#define N_V        2048
#define N_OBJS     32
#define ANCHORS    64
#define KNN        16
#define FPS_THREADS 256
#define PPT        8            // points per thread in FPS (2048/256)
#define FULL       0xffffffffu

__device__ int g_anchors[N_OBJS * ANCHORS];

// ---------------------------------------------------------------------------
// Kernel 1: farthest point sampling, one block per object.
// (byte-exact the R1/R2 version — the fastest measured fps configuration)
// ---------------------------------------------------------------------------
__global__ __launch_bounds__(FPS_THREADS) void fps_kernel(const float* __restrict__ pos) {
    const int o = blockIdx.x;
    const float* __restrict__ P = pos + (size_t)o * N_V * 3;

    __shared__ float spts[N_V * 3];                       // 24 KB
    __shared__ unsigned long long swk[2][FPS_THREADS / 32];

    const int tid  = threadIdx.x;
    const int lane = tid & 31;
    const int wid  = tid >> 5;

    for (int i = tid; i < N_V * 3; i += FPS_THREADS) spts[i] = P[i];
    __syncthreads();

    float px[PPT], py[PPT], pz[PPT], md[PPT];
    const float x0 = spts[0], y0 = spts[1], z0 = spts[2];
#pragma unroll
    for (int k = 0; k < PPT; k++) {
        const int j = tid + FPS_THREADS * k;
        px[k] = spts[j * 3 + 0];
        py[k] = spts[j * 3 + 1];
        pz[k] = spts[j * 3 + 2];
        const float dx = px[k] - x0, dy = py[k] - y0, dz = pz[k] - z0;
        md[k] = dx * dx + dy * dy + dz * dz;              // matches reference FPS formula
    }
    if (tid == 0) g_anchors[o * ANCHORS + 0] = 0;

    int buf = 0;
    for (int it = 1; it < ANCHORS; ++it) {
        // local argmax over my 8 points
        float bv = md[0];
        int   bi = tid;
#pragma unroll
        for (int k = 1; k < PPT; k++) {
            if (md[k] > bv) { bv = md[k]; bi = tid + FPS_THREADS * k; }
        }
        // warp argmax: md >= 0 so raw float bits are monotonic as unsigned
        const unsigned u = __float_as_uint(bv);
        const unsigned m = __reduce_max_sync(FULL, u);
        const unsigned bal = __ballot_sync(FULL, u == m);
        const int src = __ffs(bal) - 1;
        const int ci  = __shfl_sync(FULL, bi, src);
        if (lane == 0)
            swk[buf][wid] = ((unsigned long long)m << 32) | (unsigned)(0x7FFFFFFF - ci);
        __syncthreads();

        // every thread reduces the 8 warp partials (no second barrier needed)
        unsigned long long best = swk[buf][0];
#pragma unroll
        for (int w = 1; w < FPS_THREADS / 32; w++) {
            const unsigned long long c = swk[buf][w];
            if (c > best) best = c;
        }
        const int bidx = 0x7FFFFFFF - (int)(unsigned)(best & 0xFFFFFFFFull);
        if (tid == 0) g_anchors[o * ANCHORS + it] = bidx;

        const float qx = spts[bidx * 3 + 0];
        const float qy = spts[bidx * 3 + 1];
        const float qz = spts[bidx * 3 + 2];
#pragma unroll
        for (int k = 0; k < PPT; k++) {
            const float dx = px[k] - qx, dy = py[k] - qy, dz = pz[k] - qz;
            const float d = dx * dx + dy * dy + dz * dz;
            md[k] = fminf(md[k], d);
        }
        buf ^= 1;
    }
}

// monotonic total-order key for floats (handles tiny negative d2 from cancellation)
__device__ __forceinline__ unsigned fkey(float f) {
    const unsigned u = __float_as_uint(f);
    return (u & 0x80000000u) ? ~u : (u | 0x80000000u);
}

// ---------------------------------------------------------------------------
// Kernel 2: KNN at anchors + gather + output assembly.
// One BLOCK (512 thr) per 4 anchors of ONE object. The object's 2048 points
// are staged to SMEM once; each 128-thread group then runs the R2-proven
// selection for its anchor entirely from SMEM (29-cyc conflict-free LDS,
// stride-3 hits all 32 banks) — the strided-LDG latency that set the 18 us
// floor is gone, and gmem traffic per anchor drops 4x. The accumulation
// pass RECOMPUTES distances from the same smem values with the same
// expression (bit-identical d<=T decisions; no distance park needed).
// Selection + distance arithmetic byte-identical to R2 (rel_err 4.7e-8).
// ---------------------------------------------------------------------------
__global__ __launch_bounds__(512, 2) void knn_kernel(const float* __restrict__ pos,
                                                     const float* __restrict__ vel,
                                                     const float* __restrict__ phys,
                                                     const float* __restrict__ refp,
                                                     float* __restrict__ out) {
    __shared__ __align__(16) float spts[N_V * 3];         // 24 KB staged points
    __shared__ float cand[4][4 * KNN];
    __shared__ float sT[4];
    __shared__ float psum[4][4][3];

    const int tid  = threadIdx.x;
    const int grp  = tid >> 7;                   // anchor group 0..3
    const int t    = tid & 127;                  // thread within group
    const int lane = t & 31;
    const int wid  = t >> 5;                     // warp within group 0..3

    const int a   = blockIdx.x * 4 + grp;        // global anchor id [0, 2048)
    const int obj = a >> 6;                      // all 4 anchors share one object
    const int aidx = g_anchors[a];               // issued early; used after barrier

    // ---- stage this object's points (1536 float4 = 3 per thread) ----
    {
        const float* __restrict__ P = pos + (size_t)obj * N_V * 3;
        const float4* __restrict__ P4 = (const float4*)P;
        float4* S4 = (float4*)spts;
        for (int i = tid; i < (N_V * 3) / 4; i += 512) S4[i] = P4[i];
    }
    __syncthreads();

    const float qx = spts[aidx * 3 + 0];
    const float qy = spts[aidx * 3 + 1];
    const float qz = spts[aidx * 3 + 2];
    const float sqq = qx * qx + qy * qy + qz * qz;

    const int base = wid << 9;                   // this warp's 512-point chunk

    // ---- distances for my 16 points (expression identical to R2) ----
    float v[KNN];
#pragma unroll 4
    for (int k = 0; k < KNN; k++) {
        const int j = base + (k << 5) + lane;
        const float x = spts[j * 3 + 0], y = spts[j * 3 + 1], z = spts[j * 3 + 2];
        float d = (x * x + y * y + z * z + sqq) - 2.0f * (x * qx + y * qy + z * qz);
        if (j == aidx) d += 1e10f;               // reference's diagonal exclusion
        v[k] = d;
    }

    // ---- bitonic sort of the 16 values (ascending), value-only ----
#pragma unroll
    for (int kk = 2; kk <= KNN; kk <<= 1) {
#pragma unroll
        for (int jj = kk >> 1; jj > 0; jj >>= 1) {
#pragma unroll
            for (int i = 0; i < KNN; i++) {
                const int l = i ^ jj;
                if (l > i) {
                    const float va = v[i], vb = v[l];
                    const float lo = fminf(va, vb), hi = fmaxf(va, vb);
                    const bool up = ((i & kk) == 0);
                    v[i] = up ? lo : hi;
                    v[l] = up ? hi : lo;
                }
            }
        }
    }

    // ---- per-warp pop-min extraction: 16 smallest of this warp's 512 ----
    const float FINF = __int_as_float(0x7f800000);
#pragma unroll
    for (int r = 0; r < KNN; r++) {
        const unsigned key = fkey(v[0]);
        const unsigned km  = __reduce_min_sync(FULL, key);
        const unsigned bal = __ballot_sync(FULL, key == km);
        const int win = __ffs(bal) - 1;
        if (lane == win) {
            cand[grp][(wid << 4) + r] = v[0];
#pragma unroll
            for (int tt = 0; tt < KNN - 1; tt++) v[tt] = v[tt + 1];
            v[KNN - 1] = FINF;
        }
    }
    __syncthreads();

    // ---- warp 0 of each group: T = 16th smallest of the 64 candidates ----
    if (wid == 0) {
        float c0 = cand[grp][lane * 2], c1 = cand[grp][lane * 2 + 1];
        float T = 0.0f;
#pragma unroll
        for (int r = 0; r < KNN; r++) {
            const unsigned key = fkey(c0);
            const unsigned km  = __reduce_min_sync(FULL, key);
            const unsigned bal = __ballot_sync(FULL, key == km);
            const int win = __ffs(bal) - 1;
            T = __shfl_sync(FULL, c0, win);
            if (lane == win) { c0 = c1; c1 = FINF; }
        }
        if (lane == 0) sT[grp] = T;
    }
    __syncthreads();
    const float T = sT[grp];

    // ---- accumulate positions with d <= T (distance recomputed from the
    //      same smem values with the same expression -> identical bits) ----
    float sx = 0.f, sy = 0.f, sz = 0.f;
#pragma unroll 4
    for (int k = 0; k < KNN; k++) {
        const int j = base + (k << 5) + lane;
        const float x = spts[j * 3 + 0], y = spts[j * 3 + 1], z = spts[j * 3 + 2];
        float d = (x * x + y * y + z * z + sqq) - 2.0f * (x * qx + y * qy + z * qz);
        if (j == aidx) d += 1e10f;
        if (d <= T) { sx += x; sy += y; sz += z; }
    }
#pragma unroll
    for (int off = 16; off; off >>= 1) {
        sx += __shfl_xor_sync(FULL, sx, off);
        sy += __shfl_xor_sync(FULL, sy, off);
        sz += __shfl_xor_sync(FULL, sz, off);
    }
    if (lane == 0) { psum[grp][wid][0] = sx; psum[grp][wid][1] = sy; psum[grp][wid][2] = sz; }
    __syncthreads();

    if (t == 0) {
        const float nx = psum[grp][0][0] + psum[grp][1][0] + psum[grp][2][0] + psum[grp][3][0];
        const float ny = psum[grp][0][1] + psum[grp][1][1] + psum[grp][2][1] + psum[grp][3][1];
        const float nz = psum[grp][0][2] + psum[grp][1][2] + psum[grp][2][2] + psum[grp][3][2];
        float* __restrict__ o = out + (size_t)a * 12;
        const float inv = 1.0f / 16.0f;
        // anchor_dist: mean(neigh) - p
        o[0] = nx * inv - qx;
        o[1] = ny * inv - qy;
        o[2] = nz * inv - qz;
        // anchor_vel
        const float* __restrict__ V = vel + (size_t)obj * N_V * 3;
        o[3] = V[aidx * 3 + 0];
        o[4] = V[aidx * 3 + 1];
        o[5] = V[aidx * 3 + 2];
        // anchor_rel = pos - ref
        const float* __restrict__ R = refp + (size_t)obj * N_V * 3;
        o[6] = qx - R[aidx * 3 + 0];
        o[7] = qy - R[aidx * 3 + 1];
        o[8] = qz - R[aidx * 3 + 2];
        // physics broadcast
        o[9]  = phys[obj * 3 + 0];
        o[10] = phys[obj * 3 + 1];
        o[11] = phys[obj * 3 + 2];
    }
}

extern "C" void kernel_launch(void* const* d_in, const int* in_sizes, int n_in,
                              void* d_out, int out_size) {
    const float* positions  = (const float*)d_in[0];
    const float* velocities = (const float*)d_in[1];
    const float* physics    = (const float*)d_in[2];
    const float* refpos     = (const float*)d_in[3];
    float* out = (float*)d_out;

    fps_kernel<<<N_OBJS, FPS_THREADS>>>(positions);
    knn_kernel<<<(N_OBJS * ANCHORS) / 4, 512>>>(positions, velocities, physics, refpos, out);
}

// round 13
// speedup vs baseline: 4.6865x; 1.0008x over previous
#include <cuda_runtime.h>

// Problem constants (B=4, N_obj=8 -> 32 objects, N_v=2048 points, 64 anchors, 16-NN)
#define N_V        2048
#define N_OBJS     32
#define ANCHORS    64
#define KNN        16
#define FPS_THREADS 256
#define PPT        8            // points per thread in FPS (2048/256)
#define FULL       0xffffffffu

__device__ int g_anchors[N_OBJS * ANCHORS];

// ---------------------------------------------------------------------------
// Kernel 1: farthest point sampling, one block per object.
// (byte-exact the R1/R2 version — the fastest measured fps configuration)
// ---------------------------------------------------------------------------
__global__ __launch_bounds__(FPS_THREADS) void fps_kernel(const float* __restrict__ pos) {
    const int o = blockIdx.x;
    const float* __restrict__ P = pos + (size_t)o * N_V * 3;

    __shared__ float spts[N_V * 3];                       // 24 KB
    __shared__ unsigned long long swk[2][FPS_THREADS / 32];

    const int tid  = threadIdx.x;
    const int lane = tid & 31;
    const int wid  = tid >> 5;

    for (int i = tid; i < N_V * 3; i += FPS_THREADS) spts[i] = P[i];
    __syncthreads();

    float px[PPT], py[PPT], pz[PPT], md[PPT];
    const float x0 = spts[0], y0 = spts[1], z0 = spts[2];
#pragma unroll
    for (int k = 0; k < PPT; k++) {
        const int j = tid + FPS_THREADS * k;
        px[k] = spts[j * 3 + 0];
        py[k] = spts[j * 3 + 1];
        pz[k] = spts[j * 3 + 2];
        const float dx = px[k] - x0, dy = py[k] - y0, dz = pz[k] - z0;
        md[k] = dx * dx + dy * dy + dz * dz;              // matches reference FPS formula
    }
    if (tid == 0) g_anchors[o * ANCHORS + 0] = 0;

    int buf = 0;
    for (int it = 1; it < ANCHORS; ++it) {
        // local argmax over my 8 points
        float bv = md[0];
        int   bi = tid;
#pragma unroll
        for (int k = 1; k < PPT; k++) {
            if (md[k] > bv) { bv = md[k]; bi = tid + FPS_THREADS * k; }
        }
        // warp argmax: md >= 0 so raw float bits are monotonic as unsigned
        const unsigned u = __float_as_uint(bv);
        const unsigned m = __reduce_max_sync(FULL, u);
        const unsigned bal = __ballot_sync(FULL, u == m);
        const int src = __ffs(bal) - 1;
        const int ci  = __shfl_sync(FULL, bi, src);
        if (lane == 0)
            swk[buf][wid] = ((unsigned long long)m << 32) | (unsigned)(0x7FFFFFFF - ci);
        __syncthreads();

        // every thread reduces the 8 warp partials (no second barrier needed)
        unsigned long long best = swk[buf][0];
#pragma unroll
        for (int w = 1; w < FPS_THREADS / 32; w++) {
            const unsigned long long c = swk[buf][w];
            if (c > best) best = c;
        }
        const int bidx = 0x7FFFFFFF - (int)(unsigned)(best & 0xFFFFFFFFull);
        if (tid == 0) g_anchors[o * ANCHORS + it] = bidx;

        const float qx = spts[bidx * 3 + 0];
        const float qy = spts[bidx * 3 + 1];
        const float qz = spts[bidx * 3 + 2];
#pragma unroll
        for (int k = 0; k < PPT; k++) {
            const float dx = px[k] - qx, dy = py[k] - qy, dz = pz[k] - qz;
            const float d = dx * dx + dy * dy + dz * dz;
            md[k] = fminf(md[k], d);
        }
        buf ^= 1;
    }
}

// monotonic total-order key for floats (handles tiny negative d2 from cancellation)
__device__ __forceinline__ unsigned fkey(float f) {
    const unsigned u = __float_as_uint(f);
    return (u & 0x80000000u) ? ~u : (u | 0x80000000u);
}
__device__ __forceinline__ float unfkey(unsigned k) {     // exact inverse of fkey
    return __uint_as_float((k & 0x80000000u) ? (k & 0x7FFFFFFFu) : ~k);
}

// ---------------------------------------------------------------------------
// Kernel 2: KNN at anchors + gather + output assembly. R2 body with two
// safe deltas:
//   (1) lane owns 16 CONTIGUOUS points loaded as 12 x LDG.128 (static
//       component extraction, chunk-wise so only 3 float4 are live);
//       accumulation reloads the same L1-hot float4s. Pure load-path
//       change — selection multiset identical.
//   (2) warp0 merge keeps ballot+ffs winner selection (tie-safe, R12's
//       lesson) but decodes T = unfkey(km) after the loop instead of a
//       per-round shfl broadcast (fkey is a bijection -> exact).
// Pop rounds keep full ballot+ffs (ties exist — twice proven).
// Distance expression bit-identical to R2.
// ---------------------------------------------------------------------------
__global__ __launch_bounds__(128) void knn_kernel(const float* __restrict__ pos,
                                                  const float* __restrict__ vel,
                                                  const float* __restrict__ phys,
                                                  const float* __restrict__ refp,
                                                  float* __restrict__ out) {
    __shared__ float cand[4 * KNN];
    __shared__ float sT;
    __shared__ float psum[4][3];

    const int a    = blockIdx.x;                 // global anchor id [0, 2048)
    const int tid  = threadIdx.x;
    const int lane = tid & 31;
    const int wid  = tid >> 5;
    const int obj  = a >> 6;
    const int aidx = g_anchors[a];

    const float* __restrict__ P = pos + (size_t)obj * N_V * 3;
    const float qx = P[aidx * 3 + 0];
    const float qy = P[aidx * 3 + 1];
    const float qz = P[aidx * 3 + 2];
    const float sqq = qx * qx + qy * qy + qz * qz;

    // my 16 contiguous points: global ids [pbase, pbase+16)
    const int pbase = (wid << 9) + (lane << 4);
    const float4* __restrict__ Pw = (const float4*)(P + (size_t)pbase * 3);

    // ---- distances, chunk-wise (4 points per 3 float4); expression = R2 ----
    float d[KNN], v[KNN];
#pragma unroll
    for (int c = 0; c < 4; c++) {
        const float4 A = Pw[3 * c], B = Pw[3 * c + 1], C = Pw[3 * c + 2];
        const float xs[4] = {A.x, A.w, B.z, C.y};
        const float ys[4] = {A.y, B.x, B.w, C.z};
        const float zs[4] = {A.z, B.y, C.x, C.w};
#pragma unroll
        for (int t = 0; t < 4; t++) {
            const int k = 4 * c + t;
            const float x = xs[t], y = ys[t], z = zs[t];
            float dd = (x * x + y * y + z * z + sqq) - 2.0f * (x * qx + y * qy + z * qz);
            if (pbase + k == aidx) dd += 1e10f;  // reference's diagonal exclusion
            d[k] = dd; v[k] = dd;
        }
    }

    // ---- bitonic sort of the 16 values (ascending), value-only ----
#pragma unroll
    for (int kk = 2; kk <= KNN; kk <<= 1) {
#pragma unroll
        for (int jj = kk >> 1; jj > 0; jj >>= 1) {
#pragma unroll
            for (int i = 0; i < KNN; i++) {
                const int l = i ^ jj;
                if (l > i) {
                    const float va = v[i], vb = v[l];
                    const float lo = fminf(va, vb), hi = fmaxf(va, vb);
                    const bool up = ((i & kk) == 0);
                    v[i] = up ? lo : hi;
                    v[l] = up ? hi : lo;
                }
            }
        }
    }

    // ---- per-warp pop-min extraction: 16 smallest of this warp's 512.
    //      ballot+ffs single winner (MANDATORY — ties exist, R3/R12). ----
    const float FINF = __int_as_float(0x7f800000);
#pragma unroll
    for (int r = 0; r < KNN; r++) {
        const unsigned key = fkey(v[0]);
        const unsigned km  = __reduce_min_sync(FULL, key);
        const unsigned bal = __ballot_sync(FULL, key == km);
        const int win = __ffs(bal) - 1;
        if (lane == win) {
            cand[(wid << 4) + r] = v[0];
#pragma unroll
            for (int t = 0; t < KNN - 1; t++) v[t] = v[t + 1];
            v[KNN - 1] = FINF;
        }
    }
    __syncthreads();

    // ---- warp 0: T = 16th smallest of the 64 candidates. Winner selection
    //      keeps ballot+ffs; T decoded from the last round's km (exact). ----
    if (wid == 0) {
        float c0 = cand[lane * 2], c1 = cand[lane * 2 + 1];
        unsigned kmLast = 0;
#pragma unroll
        for (int r = 0; r < KNN; r++) {
            const unsigned key = fkey(c0);
            const unsigned km  = __reduce_min_sync(FULL, key);
            const unsigned bal = __ballot_sync(FULL, key == km);
            const int win = __ffs(bal) - 1;
            if (lane == win) { c0 = c1; c1 = FINF; }
            kmLast = km;
        }
        if (lane == 0) sT = unfkey(kmLast);
    }
    __syncthreads();
    const float T = sT;

    // ---- accumulate positions of the 16 selected points (L1-hot reload) ----
    float sx = 0.f, sy = 0.f, sz = 0.f;
#pragma unroll
    for (int c = 0; c < 4; c++) {
        const float4 A = Pw[3 * c], B = Pw[3 * c + 1], C = Pw[3 * c + 2];
        const float xs[4] = {A.x, A.w, B.z, C.y};
        const float ys[4] = {A.y, B.x, B.w, C.z};
        const float zs[4] = {A.z, B.y, C.x, C.w};
#pragma unroll
        for (int t = 0; t < 4; t++) {
            const int k = 4 * c + t;
            if (d[k] <= T) { sx += xs[t]; sy += ys[t]; sz += zs[t]; }
        }
    }
#pragma unroll
    for (int off = 16; off; off >>= 1) {
        sx += __shfl_xor_sync(FULL, sx, off);
        sy += __shfl_xor_sync(FULL, sy, off);
        sz += __shfl_xor_sync(FULL, sz, off);
    }
    if (lane == 0) { psum[wid][0] = sx; psum[wid][1] = sy; psum[wid][2] = sz; }
    __syncthreads();

    if (tid == 0) {
        const float nx = psum[0][0] + psum[1][0] + psum[2][0] + psum[3][0];
        const float ny = psum[0][1] + psum[1][1] + psum[2][1] + psum[3][1];
        const float nz = psum[0][2] + psum[1][2] + psum[2][2] + psum[3][2];
        float* __restrict__ o = out + (size_t)a * 12;
        const float inv = 1.0f / 16.0f;
        // anchor_dist: mean(neigh) - p
        o[0] = nx * inv - qx;
        o[1] = ny * inv - qy;
        o[2] = nz * inv - qz;
        // anchor_vel
        const float* __restrict__ V = vel + (size_t)obj * N_V * 3;
        o[3] = V[aidx * 3 + 0];
        o[4] = V[aidx * 3 + 1];
        o[5] = V[aidx * 3 + 2];
        // anchor_rel = pos - ref
        const float* __restrict__ R = refp + (size_t)obj * N_V * 3;
        o[6] = qx - R[aidx * 3 + 0];
        o[7] = qy - R[aidx * 3 + 1];
        o[8] = qz - R[aidx * 3 + 2];
        // physics broadcast
        o[9]  = phys[obj * 3 + 0];
        o[10] = phys[obj * 3 + 1];
        o[11] = phys[obj * 3 + 2];
    }
}

extern "C" void kernel_launch(void* const* d_in, const int* in_sizes, int n_in,
                              void* d_out, int out_size) {
    const float* positions  = (const float*)d_in[0];
    const float* velocities = (const float*)d_in[1];
    const float* physics    = (const float*)d_in[2];
    const float* refpos     = (const float*)d_in[3];
    float* out = (float*)d_out;

    fps_kernel<<<N_OBJS, FPS_THREADS>>>(positions);
    knn_kernel<<<N_OBJS * ANCHORS, 128>>>(positions, velocities, physics, refpos, out);
}

// round 14
// speedup vs baseline: 5.1651x; 1.1021x over previous
#include <cuda_runtime.h>

// Problem constants (B=4, N_obj=8 -> 32 objects, N_v=2048 points, 64 anchors, 16-NN)
#define N_V        2048
#define N_OBJS     32
#define ANCHORS    64
#define KNN        16
#define FPS_THREADS 256
#define PPT        8            // points per thread in FPS (2048/256)
#define FULL       0xffffffffu

// per-anchor pack: (qx, qy, qz, bitcast(anchor_index))
__device__ float4 g_qpack[N_OBJS * ANCHORS];

// ---------------------------------------------------------------------------
// Kernel 1: farthest point sampling, one block per object (R2-proven body).
// Anchors accumulate in SMEM; a light tail publishes the per-anchor query
// pack (3 LDS + 1 STG.128 per anchor — nothing else; R9's tail regression
// came from its vel/ref gathers, which stay in knn here).
// ---------------------------------------------------------------------------
__global__ __launch_bounds__(FPS_THREADS) void fps_kernel(const float* __restrict__ pos) {
    const int o = blockIdx.x;
    const float* __restrict__ P = pos + (size_t)o * N_V * 3;

    __shared__ float spts[N_V * 3];                       // 24 KB
    __shared__ unsigned long long swk[2][FPS_THREADS / 32];
    __shared__ int sanch[ANCHORS];

    const int tid  = threadIdx.x;
    const int lane = tid & 31;
    const int wid  = tid >> 5;

    for (int i = tid; i < N_V * 3; i += FPS_THREADS) spts[i] = P[i];
    __syncthreads();

    float px[PPT], py[PPT], pz[PPT], md[PPT];
    const float x0 = spts[0], y0 = spts[1], z0 = spts[2];
#pragma unroll
    for (int k = 0; k < PPT; k++) {
        const int j = tid + FPS_THREADS * k;
        px[k] = spts[j * 3 + 0];
        py[k] = spts[j * 3 + 1];
        pz[k] = spts[j * 3 + 2];
        const float dx = px[k] - x0, dy = py[k] - y0, dz = pz[k] - z0;
        md[k] = dx * dx + dy * dy + dz * dz;              // matches reference FPS formula
    }
    if (tid == 0) sanch[0] = 0;

    int buf = 0;
    for (int it = 1; it < ANCHORS; ++it) {
        // local argmax over my 8 points
        float bv = md[0];
        int   bi = tid;
#pragma unroll
        for (int k = 1; k < PPT; k++) {
            if (md[k] > bv) { bv = md[k]; bi = tid + FPS_THREADS * k; }
        }
        // warp argmax: md >= 0 so raw float bits are monotonic as unsigned
        const unsigned u = __float_as_uint(bv);
        const unsigned m = __reduce_max_sync(FULL, u);
        const unsigned bal = __ballot_sync(FULL, u == m);
        const int src = __ffs(bal) - 1;
        const int ci  = __shfl_sync(FULL, bi, src);
        if (lane == 0)
            swk[buf][wid] = ((unsigned long long)m << 32) | (unsigned)(0x7FFFFFFF - ci);
        __syncthreads();

        // every thread reduces the 8 warp partials (no second barrier needed)
        unsigned long long best = swk[buf][0];
#pragma unroll
        for (int w = 1; w < FPS_THREADS / 32; w++) {
            const unsigned long long c = swk[buf][w];
            if (c > best) best = c;
        }
        const int bidx = 0x7FFFFFFF - (int)(unsigned)(best & 0xFFFFFFFFull);
        if (tid == 0) sanch[it] = bidx;

        const float qx = spts[bidx * 3 + 0];
        const float qy = spts[bidx * 3 + 1];
        const float qz = spts[bidx * 3 + 2];
#pragma unroll
        for (int k = 0; k < PPT; k++) {
            const float dx = px[k] - qx, dy = py[k] - qy, dz = pz[k] - qz;
            const float d = dx * dx + dy * dy + dz * dz;
            md[k] = fminf(md[k], d);
        }
        buf ^= 1;
    }
    __syncthreads();                                      // sanch complete

    // light tail: publish (q, aidx) packs — 64 threads, 3 LDS + 1 STG.128
    if (tid < ANCHORS) {
        const int aidx = sanch[tid];
        g_qpack[o * ANCHORS + tid] = make_float4(spts[aidx * 3 + 0],
                                                 spts[aidx * 3 + 1],
                                                 spts[aidx * 3 + 2],
                                                 __int_as_float(aidx));
    }
}

// monotonic total-order key for floats (handles tiny negative d2 from cancellation)
__device__ __forceinline__ unsigned fkey(float f) {
    const unsigned u = __float_as_uint(f);
    return (u & 0x80000000u) ? ~u : (u | 0x80000000u);
}
__device__ __forceinline__ float unfkey(unsigned k) {     // exact inverse of fkey
    return __uint_as_float((k & 0x80000000u) ? (k & 0x7FFFFFFFu) : ~k);
}

// ---------------------------------------------------------------------------
// Kernel 2: KNN at anchors + gather + output assembly — byte-exact the R2
// champion body (strided scalar loads, register d[]/v[], bitonic sort,
// ballot+ffs pop rounds) with exactly two isolated deltas:
//   (1) prologue = ONE LDG.128 of the fps-published qpack (replaces the
//       dependent g_anchors -> P[aidx] load chain)
//   (2) warp0 merge decodes T = unfkey(km_last) (exact; winner selection
//       keeps ballot+ffs — value ties are real, proven R3/R12)
// ---------------------------------------------------------------------------
__global__ __launch_bounds__(128) void knn_kernel(const float* __restrict__ pos,
                                                  const float* __restrict__ vel,
                                                  const float* __restrict__ phys,
                                                  const float* __restrict__ refp,
                                                  float* __restrict__ out) {
    __shared__ float cand[4 * KNN];
    __shared__ float sT;
    __shared__ float psum[4][3];

    const int a    = blockIdx.x;                 // global anchor id [0, 2048)
    const int tid  = threadIdx.x;
    const int lane = tid & 31;
    const int wid  = tid >> 5;
    const int obj  = a >> 6;

    const float4 qp = g_qpack[a];                // single 16B load: q + aidx
    const float qx = qp.x, qy = qp.y, qz = qp.z;
    const int aidx = __float_as_int(qp.w);
    const float sqq = qx * qx + qy * qy + qz * qz;

    const float* __restrict__ P = pos + (size_t)obj * N_V * 3;
    const int base = wid << 9;                   // this warp's 512-point chunk

    // ---- distances for my 16 points (kept in d[]; v[] is scratch) ----
    float d[KNN], v[KNN];
#pragma unroll
    for (int k = 0; k < KNN; k++) {
        const int j = base + (k << 5) + lane;
        const float x = P[j * 3 + 0], y = P[j * 3 + 1], z = P[j * 3 + 2];
        float dd = (x * x + y * y + z * z + sqq) - 2.0f * (x * qx + y * qy + z * qz);
        if (j == aidx) dd += 1e10f;              // reference's diagonal exclusion
        d[k] = dd; v[k] = dd;
    }

    // ---- bitonic sort of the 16 values (ascending), value-only ----
#pragma unroll
    for (int kk = 2; kk <= KNN; kk <<= 1) {
#pragma unroll
        for (int jj = kk >> 1; jj > 0; jj >>= 1) {
#pragma unroll
            for (int i = 0; i < KNN; i++) {
                const int l = i ^ jj;
                if (l > i) {
                    const float va = v[i], vb = v[l];
                    const float lo = fminf(va, vb), hi = fmaxf(va, vb);
                    const bool up = ((i & kk) == 0);
                    v[i] = up ? lo : hi;
                    v[l] = up ? hi : lo;
                }
            }
        }
    }

    // ---- per-warp pop-min extraction: 16 smallest of this warp's 512.
    //      ballot+ffs single winner (MANDATORY — ties exist, R3/R12). ----
    const float FINF = __int_as_float(0x7f800000);
#pragma unroll
    for (int r = 0; r < KNN; r++) {
        const unsigned key = fkey(v[0]);
        const unsigned km  = __reduce_min_sync(FULL, key);
        const unsigned bal = __ballot_sync(FULL, key == km);
        const int win = __ffs(bal) - 1;
        if (lane == win) {
            cand[(wid << 4) + r] = v[0];
#pragma unroll
            for (int t = 0; t < KNN - 1; t++) v[t] = v[t + 1];
            v[KNN - 1] = FINF;
        }
    }
    __syncthreads();

    // ---- warp 0: T = 16th smallest of the 64 candidates. Winner selection
    //      keeps ballot+ffs; T decoded from the last round's km (exact). ----
    if (wid == 0) {
        float c0 = cand[lane * 2], c1 = cand[lane * 2 + 1];
        unsigned kmLast = 0;
#pragma unroll
        for (int r = 0; r < KNN; r++) {
            const unsigned key = fkey(c0);
            const unsigned km  = __reduce_min_sync(FULL, key);
            const unsigned bal = __ballot_sync(FULL, key == km);
            const int win = __ffs(bal) - 1;
            if (lane == win) { c0 = c1; c1 = FINF; }
            kmLast = km;
        }
        if (lane == 0) sT = unfkey(kmLast);
    }
    __syncthreads();
    const float T = sT;

    // ---- accumulate positions of the 16 selected points ----
    float sx = 0.f, sy = 0.f, sz = 0.f;
#pragma unroll
    for (int k = 0; k < KNN; k++) {
        if (d[k] <= T) {
            const int j = base + (k << 5) + lane;
            sx += P[j * 3 + 0];
            sy += P[j * 3 + 1];
            sz += P[j * 3 + 2];
        }
    }
#pragma unroll
    for (int off = 16; off; off >>= 1) {
        sx += __shfl_xor_sync(FULL, sx, off);
        sy += __shfl_xor_sync(FULL, sy, off);
        sz += __shfl_xor_sync(FULL, sz, off);
    }
    if (lane == 0) { psum[wid][0] = sx; psum[wid][1] = sy; psum[wid][2] = sz; }
    __syncthreads();

    if (tid == 0) {
        const float nx = psum[0][0] + psum[1][0] + psum[2][0] + psum[3][0];
        const float ny = psum[0][1] + psum[1][1] + psum[2][1] + psum[3][1];
        const float nz = psum[0][2] + psum[1][2] + psum[2][2] + psum[3][2];
        float* __restrict__ o = out + (size_t)a * 12;
        const float inv = 1.0f / 16.0f;
        // anchor_dist: mean(neigh) - p
        o[0] = nx * inv - qx;
        o[1] = ny * inv - qy;
        o[2] = nz * inv - qz;
        // anchor_vel
        const float* __restrict__ V = vel + (size_t)obj * N_V * 3;
        o[3] = V[aidx * 3 + 0];
        o[4] = V[aidx * 3 + 1];
        o[5] = V[aidx * 3 + 2];
        // anchor_rel = pos - ref
        const float* __restrict__ R = refp + (size_t)obj * N_V * 3;
        o[6] = qx - R[aidx * 3 + 0];
        o[7] = qy - R[aidx * 3 + 1];
        o[8] = qz - R[aidx * 3 + 2];
        // physics broadcast
        o[9]  = phys[obj * 3 + 0];
        o[10] = phys[obj * 3 + 1];
        o[11] = phys[obj * 3 + 2];
    }
}

extern "C" void kernel_launch(void* const* d_in, const int* in_sizes, int n_in,
                              void* d_out, int out_size) {
    const float* positions  = (const float*)d_in[0];
    const float* velocities = (const float*)d_in[1];
    const float* physics    = (const float*)d_in[2];
    const float* refpos     = (const float*)d_in[3];
    float* out = (float*)d_out;

    fps_kernel<<<N_OBJS, FPS_THREADS>>>(positions);
    knn_kernel<<<N_OBJS * ANCHORS, 128>>>(positions, velocities, physics, refpos, out);
}

// round 15
// speedup vs baseline: 5.4973x; 1.0643x over previous
#include <cuda_runtime.h>

// Problem constants (B=4, N_obj=8 -> 32 objects, N_v=2048 points, 64 anchors, 16-NN)
#define N_V        2048
#define N_OBJS     32
#define ANCHORS    64
#define KNN        16
#define FPS_THREADS 256
#define PPT        8            // points per thread in FPS (2048/256)
#define FULL       0xffffffffu

// per-anchor pack: (qx, qy, qz, bitcast(anchor_index))
__device__ float4 g_qpack[N_OBJS * ANCHORS];

// ---- packed f32x2 helpers (sm_103a FFMA2 path; per-element IEEE RN).
//      Op sequence bit-verified in R5 (rel_err identical to scalar). ----
__device__ __forceinline__ unsigned long long pk2(float lo, float hi) {
    unsigned long long r; asm("mov.b64 %0,{%1,%2};" : "=l"(r) : "f"(lo), "f"(hi)); return r;
}
__device__ __forceinline__ void upk2(unsigned long long v, float& lo, float& hi) {
    asm("mov.b64 {%0,%1},%2;" : "=f"(lo), "=f"(hi) : "l"(v));
}
__device__ __forceinline__ unsigned long long add2_(unsigned long long a, unsigned long long b) {
    unsigned long long r; asm("add.rn.f32x2 %0,%1,%2;" : "=l"(r) : "l"(a), "l"(b)); return r;
}
__device__ __forceinline__ unsigned long long mul2_(unsigned long long a, unsigned long long b) {
    unsigned long long r; asm("mul.rn.f32x2 %0,%1,%2;" : "=l"(r) : "l"(a), "l"(b)); return r;
}
__device__ __forceinline__ unsigned long long fma2_(unsigned long long a, unsigned long long b,
                                                    unsigned long long c) {
    unsigned long long r; asm("fma.rn.f32x2 %0,%1,%2,%3;" : "=l"(r) : "l"(a), "l"(b), "l"(c)); return r;
}

// ---------------------------------------------------------------------------
// Kernel 1: farthest point sampling, one block (256 thr) per object.
// R14-champion body with ONE delta: the distance-update loop runs on the
// f32x2 pipe (2 points per instruction; per-SMSP fma slots 112 -> 48).
// Packed sequence = same mul,fma,fma contraction as the scalar path —
// bit-identical md values (R5-verified). Argmax/reduce/barrier/tail are
// byte-exact R14.
// ---------------------------------------------------------------------------
__global__ __launch_bounds__(FPS_THREADS) void fps_kernel(const float* __restrict__ pos) {
    const int o = blockIdx.x;
    const float* __restrict__ P = pos + (size_t)o * N_V * 3;

    __shared__ float spts[N_V * 3];                       // 24 KB
    __shared__ unsigned long long swk[2][FPS_THREADS / 32];
    __shared__ int sanch[ANCHORS];

    const int tid  = threadIdx.x;
    const int lane = tid & 31;
    const int wid  = tid >> 5;

    for (int i = tid; i < N_V * 3; i += FPS_THREADS) spts[i] = P[i];
    __syncthreads();

    // own 8 points as 4 packed coordinate pairs
    unsigned long long PX[PPT / 2], PY[PPT / 2], PZ[PPT / 2];
    float md[PPT];
#pragma unroll
    for (int p = 0; p < PPT / 2; p++) {
        const int j0 = tid + FPS_THREADS * (2 * p);
        const int j1 = tid + FPS_THREADS * (2 * p + 1);
        PX[p] = pk2(spts[j0 * 3 + 0], spts[j1 * 3 + 0]);
        PY[p] = pk2(spts[j0 * 3 + 1], spts[j1 * 3 + 1]);
        PZ[p] = pk2(spts[j0 * 3 + 2], spts[j1 * 3 + 2]);
    }
    // seed distances to point 0 (same mul,fma,fma sequence as scalar)
    {
        const float x0 = spts[0], y0 = spts[1], z0 = spts[2];
        const unsigned long long nqx = pk2(-x0, -x0);
        const unsigned long long nqy = pk2(-y0, -y0);
        const unsigned long long nqz = pk2(-z0, -z0);
#pragma unroll
        for (int p = 0; p < PPT / 2; p++) {
            const unsigned long long dx = add2_(PX[p], nqx);
            const unsigned long long dy = add2_(PY[p], nqy);
            const unsigned long long dz = add2_(PZ[p], nqz);
            unsigned long long s = mul2_(dx, dx);
            s = fma2_(dy, dy, s);
            s = fma2_(dz, dz, s);
            upk2(s, md[2 * p], md[2 * p + 1]);
        }
    }
    if (tid == 0) sanch[0] = 0;

    int buf = 0;
    for (int it = 1; it < ANCHORS; ++it) {
        // local argmax over my 8 points (same sequential strict-> scan as R2)
        float bv = md[0];
        int   bi = tid;
#pragma unroll
        for (int k = 1; k < PPT; k++) {
            if (md[k] > bv) { bv = md[k]; bi = tid + FPS_THREADS * k; }
        }
        // warp argmax: md >= 0 so raw float bits are monotonic as unsigned
        const unsigned u = __float_as_uint(bv);
        const unsigned m = __reduce_max_sync(FULL, u);
        const unsigned bal = __ballot_sync(FULL, u == m);
        const int src = __ffs(bal) - 1;
        const int ci  = __shfl_sync(FULL, bi, src);
        if (lane == 0)
            swk[buf][wid] = ((unsigned long long)m << 32) | (unsigned)(0x7FFFFFFF - ci);
        __syncthreads();

        // every thread reduces the 8 warp partials (no second barrier needed)
        unsigned long long best = swk[buf][0];
#pragma unroll
        for (int w = 1; w < FPS_THREADS / 32; w++) {
            const unsigned long long c = swk[buf][w];
            if (c > best) best = c;
        }
        const int bidx = 0x7FFFFFFF - (int)(unsigned)(best & 0xFFFFFFFFull);
        if (tid == 0) sanch[it] = bidx;

        const float qx = spts[bidx * 3 + 0];
        const float qy = spts[bidx * 3 + 1];
        const float qz = spts[bidx * 3 + 2];
        const unsigned long long nqx = pk2(-qx, -qx);
        const unsigned long long nqy = pk2(-qy, -qy);
        const unsigned long long nqz = pk2(-qz, -qz);
#pragma unroll
        for (int p = 0; p < PPT / 2; p++) {
            const unsigned long long dx = add2_(PX[p], nqx);
            const unsigned long long dy = add2_(PY[p], nqy);
            const unsigned long long dz = add2_(PZ[p], nqz);
            unsigned long long s = mul2_(dx, dx);
            s = fma2_(dy, dy, s);
            s = fma2_(dz, dz, s);
            float d0, d1; upk2(s, d0, d1);
            md[2 * p]     = fminf(md[2 * p], d0);
            md[2 * p + 1] = fminf(md[2 * p + 1], d1);
        }
        buf ^= 1;
    }
    __syncthreads();                                      // sanch complete

    // light tail: publish (q, aidx) packs — 64 threads, 3 LDS + 1 STG.128
    if (tid < ANCHORS) {
        const int aidx = sanch[tid];
        g_qpack[o * ANCHORS + tid] = make_float4(spts[aidx * 3 + 0],
                                                 spts[aidx * 3 + 1],
                                                 spts[aidx * 3 + 2],
                                                 __int_as_float(aidx));
    }
}

// monotonic total-order key for floats (handles tiny negative d2 from cancellation)
__device__ __forceinline__ unsigned fkey(float f) {
    const unsigned u = __float_as_uint(f);
    return (u & 0x80000000u) ? ~u : (u | 0x80000000u);
}
__device__ __forceinline__ float unfkey(unsigned k) {     // exact inverse of fkey
    return __uint_as_float((k & 0x80000000u) ? (k & 0x7FFFFFFFu) : ~k);
}

// ---------------------------------------------------------------------------
// Kernel 2: KNN at anchors + gather + output assembly — byte-exact the R14
// champion (qpack LDG.128 prologue; R2 strided loads + register d[]/v[];
// bitonic sort; ballot+ffs pop rounds — MANDATORY, ties exist R3/R12;
// warp0 merge with unfkey T-decode).
// ---------------------------------------------------------------------------
__global__ __launch_bounds__(128) void knn_kernel(const float* __restrict__ pos,
                                                  const float* __restrict__ vel,
                                                  const float* __restrict__ phys,
                                                  const float* __restrict__ refp,
                                                  float* __restrict__ out) {
    __shared__ float cand[4 * KNN];
    __shared__ float sT;
    __shared__ float psum[4][3];

    const int a    = blockIdx.x;                 // global anchor id [0, 2048)
    const int tid  = threadIdx.x;
    const int lane = tid & 31;
    const int wid  = tid >> 5;
    const int obj  = a >> 6;

    const float4 qp = g_qpack[a];                // single 16B load: q + aidx
    const float qx = qp.x, qy = qp.y, qz = qp.z;
    const int aidx = __float_as_int(qp.w);
    const float sqq = qx * qx + qy * qy + qz * qz;

    const float* __restrict__ P = pos + (size_t)obj * N_V * 3;
    const int base = wid << 9;                   // this warp's 512-point chunk

    // ---- distances for my 16 points (kept in d[]; v[] is scratch) ----
    float d[KNN], v[KNN];
#pragma unroll
    for (int k = 0; k < KNN; k++) {
        const int j = base + (k << 5) + lane;
        const float x = P[j * 3 + 0], y = P[j * 3 + 1], z = P[j * 3 + 2];
        float dd = (x * x + y * y + z * z + sqq) - 2.0f * (x * qx + y * qy + z * qz);
        if (j == aidx) dd += 1e10f;              // reference's diagonal exclusion
        d[k] = dd; v[k] = dd;
    }

    // ---- bitonic sort of the 16 values (ascending), value-only ----
#pragma unroll
    for (int kk = 2; kk <= KNN; kk <<= 1) {
#pragma unroll
        for (int jj = kk >> 1; jj > 0; jj >>= 1) {
#pragma unroll
            for (int i = 0; i < KNN; i++) {
                const int l = i ^ jj;
                if (l > i) {
                    const float va = v[i], vb = v[l];
                    const float lo = fminf(va, vb), hi = fmaxf(va, vb);
                    const bool up = ((i & kk) == 0);
                    v[i] = up ? lo : hi;
                    v[l] = up ? hi : lo;
                }
            }
        }
    }

    // ---- per-warp pop-min extraction: 16 smallest of this warp's 512.
    //      ballot+ffs single winner (MANDATORY — ties exist, R3/R12). ----
    const float FINF = __int_as_float(0x7f800000);
#pragma unroll
    for (int r = 0; r < KNN; r++) {
        const unsigned key = fkey(v[0]);
        const unsigned km  = __reduce_min_sync(FULL, key);
        const unsigned bal = __ballot_sync(FULL, key == km);
        const int win = __ffs(bal) - 1;
        if (lane == win) {
            cand[(wid << 4) + r] = v[0];
#pragma unroll
            for (int t = 0; t < KNN - 1; t++) v[t] = v[t + 1];
            v[KNN - 1] = FINF;
        }
    }
    __syncthreads();

    // ---- warp 0: T = 16th smallest of the 64 candidates. Winner selection
    //      keeps ballot+ffs; T decoded from the last round's km (exact). ----
    if (wid == 0) {
        float c0 = cand[lane * 2], c1 = cand[lane * 2 + 1];
        unsigned kmLast = 0;
#pragma unroll
        for (int r = 0; r < KNN; r++) {
            const unsigned key = fkey(c0);
            const unsigned km  = __reduce_min_sync(FULL, key);
            const unsigned bal = __ballot_sync(FULL, key == km);
            const int win = __ffs(bal) - 1;
            if (lane == win) { c0 = c1; c1 = FINF; }
            kmLast = km;
        }
        if (lane == 0) sT = unfkey(kmLast);
    }
    __syncthreads();
    const float T = sT;

    // ---- accumulate positions of the 16 selected points ----
    float sx = 0.f, sy = 0.f, sz = 0.f;
#pragma unroll
    for (int k = 0; k < KNN; k++) {
        if (d[k] <= T) {
            const int j = base + (k << 5) + lane;
            sx += P[j * 3 + 0];
            sy += P[j * 3 + 1];
            sz += P[j * 3 + 2];
        }
    }
#pragma unroll
    for (int off = 16; off; off >>= 1) {
        sx += __shfl_xor_sync(FULL, sx, off);
        sy += __shfl_xor_sync(FULL, sy, off);
        sz += __shfl_xor_sync(FULL, sz, off);
    }
    if (lane == 0) { psum[wid][0] = sx; psum[wid][1] = sy; psum[wid][2] = sz; }
    __syncthreads();

    if (tid == 0) {
        const float nx = psum[0][0] + psum[1][0] + psum[2][0] + psum[3][0];
        const float ny = psum[0][1] + psum[1][1] + psum[2][1] + psum[3][1];
        const float nz = psum[0][2] + psum[1][2] + psum[2][2] + psum[3][2];
        float* __restrict__ o = out + (size_t)a * 12;
        const float inv = 1.0f / 16.0f;
        // anchor_dist: mean(neigh) - p
        o[0] = nx * inv - qx;
        o[1] = ny * inv - qy;
        o[2] = nz * inv - qz;
        // anchor_vel
        const float* __restrict__ V = vel + (size_t)obj * N_V * 3;
        o[3] = V[aidx * 3 + 0];
        o[4] = V[aidx * 3 + 1];
        o[5] = V[aidx * 3 + 2];
        // anchor_rel = pos - ref
        const float* __restrict__ R = refp + (size_t)obj * N_V * 3;
        o[6] = qx - R[aidx * 3 + 0];
        o[7] = qy - R[aidx * 3 + 1];
        o[8] = qz - R[aidx * 3 + 2];
        // physics broadcast
        o[9]  = phys[obj * 3 + 0];
        o[10] = phys[obj * 3 + 1];
        o[11] = phys[obj * 3 + 2];
    }
}

extern "C" void kernel_launch(void* const* d_in, const int* in_sizes, int n_in,
                              void* d_out, int out_size) {
    const float* positions  = (const float*)d_in[0];
    const float* velocities = (const float*)d_in[1];
    const float* physics    = (const float*)d_in[2];
    const float* refpos     = (const float*)d_in[3];
    float* out = (float*)d_out;

    fps_kernel<<<N_OBJS, FPS_THREADS>>>(positions);
    knn_kernel<<<N_OBJS * ANCHORS, 128>>>(positions, velocities, physics, refpos, out);
}

// round 16
// speedup vs baseline: 5.8412x; 1.0626x over previous
#include <cuda_runtime.h>

// Problem constants (B=4, N_obj=8 -> 32 objects, N_v=2048 points, 64 anchors, 16-NN)
#define N_V        2048
#define N_OBJS     32
#define ANCHORS    64
#define KNN        16
#define FPS_THREADS 256
#define PPT        8            // points per thread in FPS (2048/256)
#define FULL       0xffffffffu

// per-anchor pack: (qx, qy, qz, bitcast(anchor_index))
__device__ float4 g_qpack[N_OBJS * ANCHORS];

// ---- packed f32x2 helpers (sm_103a FFMA2 path; per-element IEEE RN).
//      Op sequence bit-verified in R5/R15 (rel_err identical to scalar). ----
__device__ __forceinline__ unsigned long long pk2(float lo, float hi) {
    unsigned long long r; asm("mov.b64 %0,{%1,%2};" : "=l"(r) : "f"(lo), "f"(hi)); return r;
}
__device__ __forceinline__ void upk2(unsigned long long v, float& lo, float& hi) {
    asm("mov.b64 {%0,%1},%2;" : "=f"(lo), "=f"(hi) : "l"(v));
}
__device__ __forceinline__ unsigned long long add2_(unsigned long long a, unsigned long long b) {
    unsigned long long r; asm("add.rn.f32x2 %0,%1,%2;" : "=l"(r) : "l"(a), "l"(b)); return r;
}
__device__ __forceinline__ unsigned long long mul2_(unsigned long long a, unsigned long long b) {
    unsigned long long r; asm("mul.rn.f32x2 %0,%1,%2;" : "=l"(r) : "l"(a), "l"(b)); return r;
}
__device__ __forceinline__ unsigned long long fma2_(unsigned long long a, unsigned long long b,
                                                    unsigned long long c) {
    unsigned long long r; asm("fma.rn.f32x2 %0,%1,%2,%3;" : "=l"(r) : "l"(a), "l"(b), "l"(c)); return r;
}

// ---------------------------------------------------------------------------
// Kernel 1: farthest point sampling, one block (256 thr) per object.
// R15 body with two fps-only deltas:
//   (a) local argmax FUSED into the seed/update loops (same ascending-k
//       strict-> scan order as the separate pass — identical result, R4-
//       proven) — removes the per-iteration 8-element scan.
//   (b) warp winner via DOUBLE REDUX: redux_max(value bits), then
//       redux_max((u==m) ? 0x7FFFFFFF-bi : 0) — every lane learns the
//       winning inverted index; lane 0 writes. Race-free, deterministic,
//       no ballot/shfl on the serial chain.
// Distance update stays on the f32x2 pipe (R15-verified bit-exact).
// ---------------------------------------------------------------------------
__global__ __launch_bounds__(FPS_THREADS) void fps_kernel(const float* __restrict__ pos) {
    const int o = blockIdx.x;
    const float* __restrict__ P = pos + (size_t)o * N_V * 3;

    __shared__ float spts[N_V * 3];                       // 24 KB
    __shared__ unsigned long long swk[2][FPS_THREADS / 32];
    __shared__ int sanch[ANCHORS];

    const int tid  = threadIdx.x;
    const int lane = tid & 31;
    const int wid  = tid >> 5;

    for (int i = tid; i < N_V * 3; i += FPS_THREADS) spts[i] = P[i];
    __syncthreads();

    // own 8 points as 4 packed coordinate pairs
    unsigned long long PX[PPT / 2], PY[PPT / 2], PZ[PPT / 2];
    float md[PPT];
    float bv = -1.0f;
    int   bi = tid;
#pragma unroll
    for (int p = 0; p < PPT / 2; p++) {
        const int j0 = tid + FPS_THREADS * (2 * p);
        const int j1 = tid + FPS_THREADS * (2 * p + 1);
        PX[p] = pk2(spts[j0 * 3 + 0], spts[j1 * 3 + 0]);
        PY[p] = pk2(spts[j0 * 3 + 1], spts[j1 * 3 + 1]);
        PZ[p] = pk2(spts[j0 * 3 + 2], spts[j1 * 3 + 2]);
    }
    // seed distances to point 0 + fused argmax (same scan order as separate)
    {
        const float x0 = spts[0], y0 = spts[1], z0 = spts[2];
        const unsigned long long nqx = pk2(-x0, -x0);
        const unsigned long long nqy = pk2(-y0, -y0);
        const unsigned long long nqz = pk2(-z0, -z0);
#pragma unroll
        for (int p = 0; p < PPT / 2; p++) {
            const unsigned long long dx = add2_(PX[p], nqx);
            const unsigned long long dy = add2_(PY[p], nqy);
            const unsigned long long dz = add2_(PZ[p], nqz);
            unsigned long long s = mul2_(dx, dx);
            s = fma2_(dy, dy, s);
            s = fma2_(dz, dz, s);
            float d0, d1; upk2(s, d0, d1);
            md[2 * p] = d0; md[2 * p + 1] = d1;
            if (d0 > bv) { bv = d0; bi = tid + FPS_THREADS * (2 * p); }
            if (d1 > bv) { bv = d1; bi = tid + FPS_THREADS * (2 * p + 1); }
        }
    }
    if (tid == 0) sanch[0] = 0;

    int buf = 0;
    for (int it = 1; it < ANCHORS; ++it) {
        // warp argmax via double redux (md >= 0 -> float bits monotonic)
        const unsigned u = __float_as_uint(bv);
        const unsigned m = __reduce_max_sync(FULL, u);
        const unsigned ci_inv =
            __reduce_max_sync(FULL, (u == m) ? (unsigned)(0x7FFFFFFF - bi) : 0u);
        if (lane == 0)
            swk[buf][wid] = ((unsigned long long)m << 32) | ci_inv;
        __syncthreads();

        // every thread reduces the 8 warp partials (no second barrier needed)
        unsigned long long best = swk[buf][0];
#pragma unroll
        for (int w = 1; w < FPS_THREADS / 32; w++) {
            const unsigned long long c = swk[buf][w];
            if (c > best) best = c;
        }
        const int bidx = 0x7FFFFFFF - (int)(unsigned)(best & 0xFFFFFFFFull);
        if (tid == 0) sanch[it] = bidx;

        const float qx = spts[bidx * 3 + 0];
        const float qy = spts[bidx * 3 + 1];
        const float qz = spts[bidx * 3 + 2];
        const unsigned long long nqx = pk2(-qx, -qx);
        const unsigned long long nqy = pk2(-qy, -qy);
        const unsigned long long nqz = pk2(-qz, -qz);
        bv = -1.0f; bi = tid;
#pragma unroll
        for (int p = 0; p < PPT / 2; p++) {
            const unsigned long long dx = add2_(PX[p], nqx);
            const unsigned long long dy = add2_(PY[p], nqy);
            const unsigned long long dz = add2_(PZ[p], nqz);
            unsigned long long s = mul2_(dx, dx);
            s = fma2_(dy, dy, s);
            s = fma2_(dz, dz, s);
            float d0, d1; upk2(s, d0, d1);
            const float m0 = fminf(md[2 * p], d0);
            const float m1 = fminf(md[2 * p + 1], d1);
            md[2 * p] = m0; md[2 * p + 1] = m1;
            if (m0 > bv) { bv = m0; bi = tid + FPS_THREADS * (2 * p); }
            if (m1 > bv) { bv = m1; bi = tid + FPS_THREADS * (2 * p + 1); }
        }
        buf ^= 1;
    }
    __syncthreads();                                      // sanch complete

    // light tail: publish (q, aidx) packs — 64 threads, 3 LDS + 1 STG.128
    if (tid < ANCHORS) {
        const int aidx = sanch[tid];
        g_qpack[o * ANCHORS + tid] = make_float4(spts[aidx * 3 + 0],
                                                 spts[aidx * 3 + 1],
                                                 spts[aidx * 3 + 2],
                                                 __int_as_float(aidx));
    }
}

// monotonic total-order key for floats (handles tiny negative d2 from cancellation)
__device__ __forceinline__ unsigned fkey(float f) {
    const unsigned u = __float_as_uint(f);
    return (u & 0x80000000u) ? ~u : (u | 0x80000000u);
}
__device__ __forceinline__ float unfkey(unsigned k) {     // exact inverse of fkey
    return __uint_as_float((k & 0x80000000u) ? (k & 0x7FFFFFFFu) : ~k);
}

// ---------------------------------------------------------------------------
// Kernel 2: KNN at anchors + gather + output assembly — byte-exact the
// R14/R15 champion (qpack LDG.128 prologue; R2 strided loads + register
// d[]/v[]; bitonic sort; ballot+ffs pop rounds — MANDATORY, ties exist
// R3/R12; warp0 merge with unfkey T-decode).
// ---------------------------------------------------------------------------
__global__ __launch_bounds__(128) void knn_kernel(const float* __restrict__ pos,
                                                  const float* __restrict__ vel,
                                                  const float* __restrict__ phys,
                                                  const float* __restrict__ refp,
                                                  float* __restrict__ out) {
    __shared__ float cand[4 * KNN];
    __shared__ float sT;
    __shared__ float psum[4][3];

    const int a    = blockIdx.x;                 // global anchor id [0, 2048)
    const int tid  = threadIdx.x;
    const int lane = tid & 31;
    const int wid  = tid >> 5;
    const int obj  = a >> 6;

    const float4 qp = g_qpack[a];                // single 16B load: q + aidx
    const float qx = qp.x, qy = qp.y, qz = qp.z;
    const int aidx = __float_as_int(qp.w);
    const float sqq = qx * qx + qy * qy + qz * qz;

    const float* __restrict__ P = pos + (size_t)obj * N_V * 3;
    const int base = wid << 9;                   // this warp's 512-point chunk

    // ---- distances for my 16 points (kept in d[]; v[] is scratch) ----
    float d[KNN], v[KNN];
#pragma unroll
    for (int k = 0; k < KNN; k++) {
        const int j = base + (k << 5) + lane;
        const float x = P[j * 3 + 0], y = P[j * 3 + 1], z = P[j * 3 + 2];
        float dd = (x * x + y * y + z * z + sqq) - 2.0f * (x * qx + y * qy + z * qz);
        if (j == aidx) dd += 1e10f;              // reference's diagonal exclusion
        d[k] = dd; v[k] = dd;
    }

    // ---- bitonic sort of the 16 values (ascending), value-only ----
#pragma unroll
    for (int kk = 2; kk <= KNN; kk <<= 1) {
#pragma unroll
        for (int jj = kk >> 1; jj > 0; jj >>= 1) {
#pragma unroll
            for (int i = 0; i < KNN; i++) {
                const int l = i ^ jj;
                if (l > i) {
                    const float va = v[i], vb = v[l];
                    const float lo = fminf(va, vb), hi = fmaxf(va, vb);
                    const bool up = ((i & kk) == 0);
                    v[i] = up ? lo : hi;
                    v[l] = up ? hi : lo;
                }
            }
        }
    }

    // ---- per-warp pop-min extraction: 16 smallest of this warp's 512.
    //      ballot+ffs single winner (MANDATORY — ties exist, R3/R12). ----
    const float FINF = __int_as_float(0x7f800000);
#pragma unroll
    for (int r = 0; r < KNN; r++) {
        const unsigned key = fkey(v[0]);
        const unsigned km  = __reduce_min_sync(FULL, key);
        const unsigned bal = __ballot_sync(FULL, key == km);
        const int win = __ffs(bal) - 1;
        if (lane == win) {
            cand[(wid << 4) + r] = v[0];
#pragma unroll
            for (int t = 0; t < KNN - 1; t++) v[t] = v[t + 1];
            v[KNN - 1] = FINF;
        }
    }
    __syncthreads();

    // ---- warp 0: T = 16th smallest of the 64 candidates. Winner selection
    //      keeps ballot+ffs; T decoded from the last round's km (exact). ----
    if (wid == 0) {
        float c0 = cand[lane * 2], c1 = cand[lane * 2 + 1];
        unsigned kmLast = 0;
#pragma unroll
        for (int r = 0; r < KNN; r++) {
            const unsigned key = fkey(c0);
            const unsigned km  = __reduce_min_sync(FULL, key);
            const unsigned bal = __ballot_sync(FULL, key == km);
            const int win = __ffs(bal) - 1;
            if (lane == win) { c0 = c1; c1 = FINF; }
            kmLast = km;
        }
        if (lane == 0) sT = unfkey(kmLast);
    }
    __syncthreads();
    const float T = sT;

    // ---- accumulate positions of the 16 selected points ----
    float sx = 0.f, sy = 0.f, sz = 0.f;
#pragma unroll
    for (int k = 0; k < KNN; k++) {
        if (d[k] <= T) {
            const int j = base + (k << 5) + lane;
            sx += P[j * 3 + 0];
            sy += P[j * 3 + 1];
            sz += P[j * 3 + 2];
        }
    }
#pragma unroll
    for (int off = 16; off; off >>= 1) {
        sx += __shfl_xor_sync(FULL, sx, off);
        sy += __shfl_xor_sync(FULL, sy, off);
        sz += __shfl_xor_sync(FULL, sz, off);
    }
    if (lane == 0) { psum[wid][0] = sx; psum[wid][1] = sy; psum[wid][2] = sz; }
    __syncthreads();

    if (tid == 0) {
        const float nx = psum[0][0] + psum[1][0] + psum[2][0] + psum[3][0];
        const float ny = psum[0][1] + psum[1][1] + psum[2][1] + psum[3][1];
        const float nz = psum[0][2] + psum[1][2] + psum[2][2] + psum[3][2];
        float* __restrict__ o = out + (size_t)a * 12;
        const float inv = 1.0f / 16.0f;
        // anchor_dist: mean(neigh) - p
        o[0] = nx * inv - qx;
        o[1] = ny * inv - qy;
        o[2] = nz * inv - qz;
        // anchor_vel
        const float* __restrict__ V = vel + (size_t)obj * N_V * 3;
        o[3] = V[aidx * 3 + 0];
        o[4] = V[aidx * 3 + 1];
        o[5] = V[aidx * 3 + 2];
        // anchor_rel = pos - ref
        const float* __restrict__ R = refp + (size_t)obj * N_V * 3;
        o[6] = qx - R[aidx * 3 + 0];
        o[7] = qy - R[aidx * 3 + 1];
        o[8] = qz - R[aidx * 3 + 2];
        // physics broadcast
        o[9]  = phys[obj * 3 + 0];
        o[10] = phys[obj * 3 + 1];
        o[11] = phys[obj * 3 + 2];
    }
}

extern "C" void kernel_launch(void* const* d_in, const int* in_sizes, int n_in,
                              void* d_out, int out_size) {
    const float* positions  = (const float*)d_in[0];
    const float* velocities = (const float*)d_in[1];
    const float* physics    = (const float*)d_in[2];
    const float* refpos     = (const float*)d_in[3];
    float* out = (float*)d_out;

    fps_kernel<<<N_OBJS, FPS_THREADS>>>(positions);
    knn_kernel<<<N_OBJS * ANCHORS, 128>>>(positions, velocities, physics, refpos, out);
}